// round 3
// baseline (speedup 1.0000x reference)
#include <cuda_runtime.h>
#include <cuda_bf16.h>
#include <cstdint>
#include <math.h>

#define DMODEL 512
#define S_LEN 1024
#define BATCH 8
#define NHEADS 8
#define NLAYERS 4
#define MSLEN 2048

// ---------------- scratch (device globals; no allocations allowed) ----------
__device__ float g_h [BATCH * S_LEN * DMODEL];       // 16 MB
__device__ float g_z [BATCH * S_LEN * 4 * DMODEL];   // 64 MB
__device__ float g_y [BATCH * S_LEN * DMODEL];       // 16 MB
__device__ float g_y2[BATCH * S_LEN * DMODEL];       // 16 MB

__device__ __forceinline__ float silu_f(float x) { return x / (1.f + expf(-x)); }

// ---------------- 1) embedding gather + target splice -----------------------
__global__ void __launch_bounds__(128) embed_kernel(
    const int* __restrict__ hist_item, const int* __restrict__ hist_cate,
    const int* __restrict__ hist_len,  const int* __restrict__ tgt_item,
    const int* __restrict__ tgt_cate,  const float* __restrict__ item_emb,
    const float* __restrict__ cate_emb, const float* __restrict__ seg_emb)
{
    int bs = blockIdx.x;
    int b = bs >> 10, s = bs & 1023;
    int hl = hist_len[b];
    int id, cid, sg;
    if (s == hl)        { id = tgt_item[b];           cid = tgt_cate[b];           sg = 1; }
    else if (s < 1023)  { id = hist_item[b*1023 + s]; cid = hist_cate[b*1023 + s]; sg = 0; }
    else                { id = 0; cid = 0; sg = 0; }
    int d = threadIdx.x * 4;
    float4 a = *(const float4*)(item_emb + (size_t)id  * DMODEL + d);
    float4 c = *(const float4*)(cate_emb + (size_t)cid * DMODEL + d);
    float4 e = *(const float4*)(seg_emb  + (size_t)sg  * DMODEL + d);
    float4 o;
    o.x = a.x + c.x + e.x; o.y = a.y + c.y + e.y;
    o.z = a.z + c.z + e.z; o.w = a.w + c.w + e.w;
    *(float4*)(g_h + (size_t)bs * DMODEL + d) = o;
}

// ---------------- 2) fp32 tiled GEMM: C[M,N] = A[M,K] @ B[K,N] + bias -------
// BM=BN=128, BK=16, 256 threads, 8x8 per-thread tile (2x2 of float4 quads).
template <int ACT>   // 0 = none, 1 = silu
__global__ void __launch_bounds__(256) gemm_kernel(
    const float* __restrict__ A, const float* __restrict__ B,
    const float* __restrict__ bias, float* __restrict__ C,
    int M, int N, int K)
{
    __shared__ float As[16][128];
    __shared__ float Bs[16][128];
    const int tid = threadIdx.x;
    const int tx = tid & 15, ty = tid >> 4;
    const int m0 = blockIdx.y * 128, n0 = blockIdx.x * 128;

    float acc[8][8];
#pragma unroll
    for (int i = 0; i < 8; i++)
#pragma unroll
        for (int j = 0; j < 8; j++) acc[i][j] = 0.f;

    const int ar = tid >> 2, ak = (tid & 3) * 4;   // A tile: 128 rows x 16 k
    const int bk = tid >> 5, bn = (tid & 31) * 4;  // B tile: 16 k x 128 cols

    for (int k0 = 0; k0 < K; k0 += 16) {
        float4 a0 = *(const float4*)(A + (size_t)(m0 + ar)      * K + k0 + ak);
        float4 a1 = *(const float4*)(A + (size_t)(m0 + ar + 64) * K + k0 + ak);
        float4 b0 = *(const float4*)(B + (size_t)(k0 + bk)     * N + n0 + bn);
        float4 b1 = *(const float4*)(B + (size_t)(k0 + bk + 8) * N + n0 + bn);
        As[ak+0][ar] = a0.x; As[ak+1][ar] = a0.y; As[ak+2][ar] = a0.z; As[ak+3][ar] = a0.w;
        As[ak+0][ar+64] = a1.x; As[ak+1][ar+64] = a1.y; As[ak+2][ar+64] = a1.z; As[ak+3][ar+64] = a1.w;
        *(float4*)&Bs[bk  ][bn] = b0;
        *(float4*)&Bs[bk+8][bn] = b1;
        __syncthreads();
#pragma unroll
        for (int kk = 0; kk < 16; kk++) {
            float a[8], bb[8];
            *(float4*)&a[0]  = *(const float4*)&As[kk][ty*4];
            *(float4*)&a[4]  = *(const float4*)&As[kk][64 + ty*4];
            *(float4*)&bb[0] = *(const float4*)&Bs[kk][tx*4];
            *(float4*)&bb[4] = *(const float4*)&Bs[kk][64 + tx*4];
#pragma unroll
            for (int i = 0; i < 8; i++)
#pragma unroll
                for (int j = 0; j < 8; j++) acc[i][j] += a[i] * bb[j];
        }
        __syncthreads();
    }

#pragma unroll
    for (int i = 0; i < 8; i++) {
        int r = m0 + ty*4 + (i & 3) + (i >> 2) * 64;
#pragma unroll
        for (int j = 0; j < 8; j++) {
            int c = n0 + tx*4 + (j & 3) + (j >> 2) * 64;
            float v = acc[i][j] + bias[c];
            if (ACT) v = silu_f(v);
            C[(size_t)r * N + c] = v;
        }
    }
}

// ---------------- 3) HSTU attention: y = (silu(QK^T + bias) * causal) @ V * U
// CTA = (s-block of 64 rows, b*8+h). t-tiles of 32. K buffer aliased as S^T.
__global__ void __launch_bounds__(256) attn_kernel(
    const float* __restrict__ Z, const float* __restrict__ pw,
    float* __restrict__ Y)
{
    __shared__ float Qs[64 * 65];   // padded: conflict-free q reads
    __shared__ float Ks[32 * 65];   // padded K; later aliased as St[t][r]
    __shared__ float Vs[32 * 64];
    __shared__ float bias_s[96];

    const int sb = blockIdx.x, bh = blockIdx.y;
    const int b = bh >> 3, h = bh & 7;
    const float* zb = Z + (size_t)b * S_LEN * 2048;
    const int s0 = sb * 64;
    const int tid = threadIdx.x;
    const int tx = tid & 15, ty = tid >> 4;   // AV-phase map (4 rows x 4 dims)
    const int cx = tid & 7,  ry = tid >> 3;   // score-phase map (2 rows x 4 t)
    const int uoff = h * 64, qoff = 512 + h * 64, koff = 1024 + h * 64, voff = 1536 + h * 64;

    // load Q tile (64x64), scalar stores into padded layout
#pragma unroll
    for (int it = 0; it < 4; it++) {
        int f = tid + it * 256;
        int r = f >> 4, c = (f & 15) * 4;
        float4 q4 = *(const float4*)(zb + (size_t)(s0 + r) * 2048 + qoff + c);
        Qs[r*65 + c+0] = q4.x; Qs[r*65 + c+1] = q4.y;
        Qs[r*65 + c+2] = q4.z; Qs[r*65 + c+3] = q4.w;
    }

    float accY[4][4];
#pragma unroll
    for (int i = 0; i < 4; i++)
#pragma unroll
        for (int j = 0; j < 4; j++) accY[i][j] = 0.f;

    const int nkt = 2 * sb + 2;
    for (int kt = 0; kt < nkt; kt++) {
        const int t0 = kt * 32;
        __syncthreads();   // prior-tile St/Vs reads done before overwrite
#pragma unroll
        for (int it = 0; it < 2; it++) {
            int f = tid + it * 256;
            int r = f >> 4, c = (f & 15) * 4;   // r in 0..31
            float4 k4 = *(const float4*)(zb + (size_t)(t0 + r) * 2048 + koff + c);
            Ks[r*65 + c+0] = k4.x; Ks[r*65 + c+1] = k4.y;
            Ks[r*65 + c+2] = k4.z; Ks[r*65 + c+3] = k4.w;
            float4 v4 = *(const float4*)(zb + (size_t)(t0 + r) * 2048 + voff + c);
            *(float4*)&Vs[r*64 + c] = v4;
        }
        const int base = MSLEN - 1 + t0 - s0;
        if (tid < 95) bias_s[tid] = pw[base - 63 + tid];
        __syncthreads();

        // scores: S[r][t] = q[r] . k[t], 64x32 tile
        float sacc[2][4];
#pragma unroll
        for (int i = 0; i < 2; i++)
#pragma unroll
            for (int j = 0; j < 4; j++) sacc[i][j] = 0.f;
#pragma unroll
        for (int d = 0; d < 64; d++) {
            float q0 = Qs[(ry*2+0)*65 + d];
            float q1 = Qs[(ry*2+1)*65 + d];
            float kv[4];
#pragma unroll
            for (int j = 0; j < 4; j++) kv[j] = Ks[(cx*4 + j)*65 + d];
#pragma unroll
            for (int j = 0; j < 4; j++) { sacc[0][j] += q0 * kv[j]; sacc[1][j] += q1 * kv[j]; }
        }
        __syncthreads();   // done reading K before aliasing as St

        // bias + silu + causal, write St[t][r] into the K buffer
#pragma unroll
        for (int i = 0; i < 2; i++) {
            int r = ry*2 + i;
#pragma unroll
            for (int j = 0; j < 4; j++) {
                int c = cx*4 + j;
                float x = sacc[i][j] + bias_s[63 + c - r];
                float sl = x / (1.f + expf(-x));
                if (t0 + c > s0 + r) sl = 0.f;
                Ks[c*65 + r] = sl;
            }
        }
        __syncthreads();

        // Y += St^T @ V
#pragma unroll
        for (int t = 0; t < 32; t++) {
            float sv[4], vv[4];
#pragma unroll
            for (int i = 0; i < 4; i++) sv[i] = Ks[t*65 + ty*4 + i];
#pragma unroll
            for (int j = 0; j < 4; j++) vv[j] = Vs[t*64 + tx*4 + j];
#pragma unroll
            for (int i = 0; i < 4; i++)
#pragma unroll
                for (int j = 0; j < 4; j++) accY[i][j] += sv[i] * vv[j];
        }
    }

    // epilogue: * u, write [B,S,D] with head h at columns h*64..
#pragma unroll
    for (int i = 0; i < 4; i++) {
        int r = ty*4 + i;
#pragma unroll
        for (int j = 0; j < 4; j++) {
            int c = tx*4 + j;
            float u = zb[(size_t)(s0 + r) * 2048 + uoff + c];
            Y[((size_t)(b * S_LEN + s0 + r)) * DMODEL + h*64 + c] = accY[i][j] * u;
        }
    }
}

// ---------------- 4) LayerNorm (optional fused residual) --------------------
__global__ void __launch_bounds__(128) ln_kernel(
    const float* __restrict__ x, const float* __restrict__ res,
    const float* __restrict__ w, const float* __restrict__ b,
    float* __restrict__ out)
{
    int row = blockIdx.x;
    int d = threadIdx.x * 4;
    size_t off = (size_t)row * DMODEL + d;
    float4 v = *(const float4*)(x + off);
    if (res) {
        float4 rv = *(const float4*)(res + off);
        v.x += rv.x; v.y += rv.y; v.z += rv.z; v.w += rv.w;
    }
    float s = v.x + v.y + v.z + v.w;
    float q = v.x*v.x + v.y*v.y + v.z*v.z + v.w*v.w;
#pragma unroll
    for (int o = 16; o > 0; o >>= 1) {
        s += __shfl_xor_sync(0xffffffffu, s, o);
        q += __shfl_xor_sync(0xffffffffu, q, o);
    }
    __shared__ float red[8];
    int warp = threadIdx.x >> 5;
    if ((threadIdx.x & 31) == 0) { red[warp] = s; red[4 + warp] = q; }
    __syncthreads();
    s = red[0] + red[1] + red[2] + red[3];
    q = red[4] + red[5] + red[6] + red[7];
    float mean = s * (1.f / 512.f);
    float var  = q * (1.f / 512.f) - mean * mean;
    float rs = rsqrtf(var + 1e-5f);
    float4 wv = *(const float4*)(w + d);
    float4 bv = *(const float4*)(b + d);
    float4 o4;
    o4.x = (v.x - mean) * rs * wv.x + bv.x;
    o4.y = (v.y - mean) * rs * wv.y + bv.y;
    o4.z = (v.z - mean) * rs * wv.z + bv.z;
    o4.w = (v.w - mean) * rs * wv.w + bv.w;
    *(float4*)(out + off) = o4;
}

// ---------------- launcher --------------------------------------------------
extern "C" void kernel_launch(void* const* d_in, const int* in_sizes, int n_in,
                              void* d_out, int out_size)
{
    (void)in_sizes; (void)n_in; (void)out_size;
    const int*   hii = (const int*)d_in[0];
    const int*   hci = (const int*)d_in[1];
    const int*   hl  = (const int*)d_in[2];
    const int*   ti  = (const int*)d_in[3];
    const int*   tc  = (const int*)d_in[4];
    const float* item_emb = (const float*)d_in[5];
    const float* cate_emb = (const float*)d_in[6];
    const float* seg_emb  = (const float*)d_in[7];
    const float* W1   = (const float*)d_in[8];
    const float* b1   = (const float*)d_in[9];
    const float* W2   = (const float*)d_in[10];
    const float* b2   = (const float*)d_in[11];
    const float* ln1w = (const float*)d_in[12];
    const float* ln1b = (const float*)d_in[13];
    const float* ln2w = (const float*)d_in[14];
    const float* ln2b = (const float*)d_in[15];
    const float* posw = (const float*)d_in[16];
    const float* lnfw = (const float*)d_in[17];
    const float* lnfb = (const float*)d_in[18];
    float* out = (float*)d_out;

    float *h_, *z_, *y_, *y2_;
    cudaGetSymbolAddress((void**)&h_,  g_h);
    cudaGetSymbolAddress((void**)&z_,  g_z);
    cudaGetSymbolAddress((void**)&y_,  g_y);
    cudaGetSymbolAddress((void**)&y2_, g_y2);

    const int ROWS = BATCH * S_LEN;  // 8192

    embed_kernel<<<ROWS, 128>>>(hii, hci, hl, ti, tc, item_emb, cate_emb, seg_emb);

    for (int l = 0; l < NLAYERS; l++) {
        gemm_kernel<1><<<dim3(2048/128, ROWS/128), 256>>>(
            h_, W1 + (size_t)l*512*2048, b1 + (size_t)l*2048, z_, ROWS, 2048, 512);
        attn_kernel<<<dim3(16, 64), 256>>>(z_, posw + (size_t)l*(2*MSLEN - 1), y_);
        ln_kernel<<<ROWS, 128>>>(y_, nullptr, ln1w + l*512, ln1b + l*512, y_);
        gemm_kernel<0><<<dim3(512/128, ROWS/128), 256>>>(
            y_, W2 + (size_t)l*512*512, b2 + (size_t)l*512, y2_, ROWS, 512, 512);
        ln_kernel<<<ROWS, 128>>>(y2_, h_, ln2w + l*512, ln2b + l*512, h_);
    }
    ln_kernel<<<ROWS, 128>>>(h_, nullptr, lnfw, lnfb, out);
}

// round 4
// speedup vs baseline: 1.0285x; 1.0285x over previous
#include <cuda_runtime.h>
#include <cuda_bf16.h>
#include <cstdint>
#include <math.h>

#define DMODEL 512
#define S_LEN 1024
#define BATCH 8
#define NHEADS 8
#define NLAYERS 4
#define MSLEN 2048

// ---------------- scratch (device globals; no allocations allowed) ----------
__device__ float g_h [BATCH * S_LEN * DMODEL];       // 16 MB
__device__ float g_z [BATCH * S_LEN * 4 * DMODEL];   // 64 MB
__device__ float g_y [BATCH * S_LEN * DMODEL];       // 16 MB
__device__ float g_y2[BATCH * S_LEN * DMODEL];       // 16 MB

// ---------------- packed f32x2 helpers (sm_10x FFMA2) ------------------------
__device__ __forceinline__ unsigned long long pk2(float lo, float hi) {
    unsigned long long r;
    asm("mov.b64 %0, {%1,%2};" : "=l"(r) : "f"(lo), "f"(hi));
    return r;
}
__device__ __forceinline__ float2 up2(unsigned long long v) {
    float2 r;
    asm("mov.b64 {%0,%1}, %2;" : "=f"(r.x), "=f"(r.y) : "l"(v));
    return r;
}
__device__ __forceinline__ void fma2(unsigned long long& d,
                                     unsigned long long a, unsigned long long b) {
    asm("fma.rn.f32x2 %0, %1, %2, %0;" : "+l"(d) : "l"(a), "l"(b));
}

__device__ __forceinline__ float silu_f(float x) {
    return __fdividef(x, 1.f + __expf(-x));
}

// ---------------- 1) embedding gather + target splice -----------------------
__global__ void __launch_bounds__(128) embed_kernel(
    const int* __restrict__ hist_item, const int* __restrict__ hist_cate,
    const int* __restrict__ hist_len,  const int* __restrict__ tgt_item,
    const int* __restrict__ tgt_cate,  const float* __restrict__ item_emb,
    const float* __restrict__ cate_emb, const float* __restrict__ seg_emb)
{
    int bs = blockIdx.x;
    int b = bs >> 10, s = bs & 1023;
    int hl = hist_len[b];
    int id, cid, sg;
    if (s == hl)        { id = tgt_item[b];           cid = tgt_cate[b];           sg = 1; }
    else if (s < 1023)  { id = hist_item[b*1023 + s]; cid = hist_cate[b*1023 + s]; sg = 0; }
    else                { id = 0; cid = 0; sg = 0; }
    int d = threadIdx.x * 4;
    float4 a = *(const float4*)(item_emb + (size_t)id  * DMODEL + d);
    float4 c = *(const float4*)(cate_emb + (size_t)cid * DMODEL + d);
    float4 e = *(const float4*)(seg_emb  + (size_t)sg  * DMODEL + d);
    float4 o;
    o.x = a.x + c.x + e.x; o.y = a.y + c.y + e.y;
    o.z = a.z + c.z + e.z; o.w = a.w + c.w + e.w;
    *(float4*)(g_h + (size_t)bs * DMODEL + d) = o;
}

// ---------------- 2) fp32 tiled GEMM w/ packed FFMA2 ------------------------
// BM=BN=128, BK=16, 256 threads, 8x8 per-thread tile, acc packed over col-pairs.
template <int ACT>   // 0 = none, 1 = silu
__global__ void __launch_bounds__(256) gemm_kernel(
    const float* __restrict__ A, const float* __restrict__ B,
    const float* __restrict__ bias, float* __restrict__ C,
    int M, int N, int K)
{
    __shared__ float As[16][128];
    __shared__ float Bs[16][128];
    const int tid = threadIdx.x;
    const int tx = tid & 15, ty = tid >> 4;
    const int m0 = blockIdx.y * 128, n0 = blockIdx.x * 128;

    unsigned long long acc[8][4];
#pragma unroll
    for (int i = 0; i < 8; i++)
#pragma unroll
        for (int j = 0; j < 4; j++) acc[i][j] = 0ull;

    const int ar = tid >> 2, ak = (tid & 3) * 4;   // A tile: 128 rows x 16 k
    const int bk = tid >> 5, bn = (tid & 31) * 4;  // B tile: 16 k x 128 cols

    for (int k0 = 0; k0 < K; k0 += 16) {
        float4 a0 = *(const float4*)(A + (size_t)(m0 + ar)      * K + k0 + ak);
        float4 a1 = *(const float4*)(A + (size_t)(m0 + ar + 64) * K + k0 + ak);
        float4 b0 = *(const float4*)(B + (size_t)(k0 + bk)     * N + n0 + bn);
        float4 b1 = *(const float4*)(B + (size_t)(k0 + bk + 8) * N + n0 + bn);
        As[ak+0][ar] = a0.x; As[ak+1][ar] = a0.y; As[ak+2][ar] = a0.z; As[ak+3][ar] = a0.w;
        As[ak+0][ar+64] = a1.x; As[ak+1][ar+64] = a1.y; As[ak+2][ar+64] = a1.z; As[ak+3][ar+64] = a1.w;
        *(float4*)&Bs[bk  ][bn] = b0;
        *(float4*)&Bs[bk+8][bn] = b1;
        __syncthreads();
#pragma unroll
        for (int kk = 0; kk < 16; kk++) {
            float4 aq0 = *(const float4*)&As[kk][ty*4];
            float4 aq1 = *(const float4*)&As[kk][64 + ty*4];
            float4 bq0 = *(const float4*)&Bs[kk][tx*4];
            float4 bq1 = *(const float4*)&Bs[kk][64 + tx*4];
            unsigned long long bb[4] = {
                pk2(bq0.x, bq0.y), pk2(bq0.z, bq0.w),
                pk2(bq1.x, bq1.y), pk2(bq1.z, bq1.w)
            };
            float a[8] = { aq0.x, aq0.y, aq0.z, aq0.w, aq1.x, aq1.y, aq1.z, aq1.w };
#pragma unroll
            for (int i = 0; i < 8; i++) {
                unsigned long long a2 = pk2(a[i], a[i]);
#pragma unroll
                for (int j = 0; j < 4; j++) fma2(acc[i][j], a2, bb[j]);
            }
        }
        __syncthreads();
    }

#pragma unroll
    for (int i = 0; i < 8; i++) {
        int r = m0 + ty*4 + (i & 3) + (i >> 2) * 64;
#pragma unroll
        for (int jp = 0; jp < 4; jp++) {
            int c = n0 + (jp >> 1) * 64 + tx*4 + (jp & 1) * 2;
            float2 v2 = up2(acc[i][jp]);
            float v0 = v2.x + bias[c];
            float v1 = v2.y + bias[c + 1];
            if (ACT) { v0 = silu_f(v0); v1 = silu_f(v1); }
            C[(size_t)r * N + c]     = v0;
            C[(size_t)r * N + c + 1] = v1;
        }
    }
}

// ---------------- 3) HSTU attention: y = (silu(QK^T + bias) * causal) @ V * U
// CTA = (s-block of 64 rows, b*8+h). t-tiles of 32. K buffer aliased as S^T.
// Even padding (66) so float2/f32x2 paths stay 8B-aligned.
__global__ void __launch_bounds__(256) attn_kernel(
    const float* __restrict__ Z, const float* __restrict__ pw,
    float* __restrict__ Y)
{
    __shared__ float Qs[64 * 66];
    __shared__ float Ks[32 * 66];   // padded K; later aliased as St[t][r]
    __shared__ float Vs[32 * 64];
    __shared__ float bias_s[96];

    const int sb = blockIdx.x, bh = blockIdx.y;
    const int b = bh >> 3, h = bh & 7;
    const float* zb = Z + (size_t)b * S_LEN * 2048;
    const int s0 = sb * 64;
    const int tid = threadIdx.x;
    const int tx = tid & 15, ty = tid >> 4;   // AV-phase map (4 rows x 4 dims)
    const int cx = tid & 7,  ry = tid >> 3;   // score-phase map (2 rows x 4 t)
    const int uoff = h * 64, qoff = 512 + h * 64, koff = 1024 + h * 64, voff = 1536 + h * 64;

    // load Q tile (64x64) into padded layout
#pragma unroll
    for (int it = 0; it < 4; it++) {
        int f = tid + it * 256;
        int r = f >> 4, c = (f & 15) * 4;
        float4 q4 = *(const float4*)(zb + (size_t)(s0 + r) * 2048 + qoff + c);
        Qs[r*66 + c+0] = q4.x; Qs[r*66 + c+1] = q4.y;
        Qs[r*66 + c+2] = q4.z; Qs[r*66 + c+3] = q4.w;
    }

    unsigned long long accY[4][2];
#pragma unroll
    for (int i = 0; i < 4; i++) { accY[i][0] = 0ull; accY[i][1] = 0ull; }

    const int nkt = 2 * sb + 2;
    for (int kt = 0; kt < nkt; kt++) {
        const int t0 = kt * 32;
        __syncthreads();   // prior-tile St/Vs reads done before overwrite
#pragma unroll
        for (int it = 0; it < 2; it++) {
            int f = tid + it * 256;
            int r = f >> 4, c = (f & 15) * 4;   // r in 0..31
            float4 k4 = *(const float4*)(zb + (size_t)(t0 + r) * 2048 + koff + c);
            Ks[r*66 + c+0] = k4.x; Ks[r*66 + c+1] = k4.y;
            Ks[r*66 + c+2] = k4.z; Ks[r*66 + c+3] = k4.w;
            float4 v4 = *(const float4*)(zb + (size_t)(t0 + r) * 2048 + voff + c);
            *(float4*)&Vs[r*64 + c] = v4;
        }
        const int base = MSLEN - 1 + t0 - s0;
        if (tid < 95) bias_s[tid] = pw[base - 63 + tid];
        __syncthreads();

        // scores: S[r][t] = q[r] . k[t], 64x32 tile; packed over d (even/odd)
        unsigned long long sa[2][4];
#pragma unroll
        for (int i = 0; i < 2; i++)
#pragma unroll
            for (int j = 0; j < 4; j++) sa[i][j] = 0ull;
#pragma unroll
        for (int d = 0; d < 64; d += 2) {
            unsigned long long q0 = *(const unsigned long long*)&Qs[(ry*2+0)*66 + d];
            unsigned long long q1 = *(const unsigned long long*)&Qs[(ry*2+1)*66 + d];
            unsigned long long kv[4];
#pragma unroll
            for (int j = 0; j < 4; j++)
                kv[j] = *(const unsigned long long*)&Ks[(cx*4 + j)*66 + d];
#pragma unroll
            for (int j = 0; j < 4; j++) {
                fma2(sa[0][j], q0, kv[j]);
                fma2(sa[1][j], q1, kv[j]);
            }
        }
        __syncthreads();   // done reading K before aliasing as St

        // bias + silu + causal, write St[t][r] into the K buffer
#pragma unroll
        for (int i = 0; i < 2; i++) {
            int r = ry*2 + i;
#pragma unroll
            for (int j = 0; j < 4; j++) {
                int c = cx*4 + j;
                float2 p = up2(sa[i][j]);
                float x = p.x + p.y + bias_s[63 + c - r];
                float sl = silu_f(x);
                if (t0 + c > s0 + r) sl = 0.f;
                Ks[c*66 + r] = sl;
            }
        }
        __syncthreads();

        // Y += St^T @ V, packed over the 4 output dims (2 pairs)
#pragma unroll
        for (int t = 0; t < 32; t++) {
            float2 s01 = *(const float2*)&Ks[t*66 + ty*4];
            float2 s23 = *(const float2*)&Ks[t*66 + ty*4 + 2];
            float4 vq  = *(const float4*)&Vs[t*64 + tx*4];
            unsigned long long v01 = pk2(vq.x, vq.y);
            unsigned long long v23 = pk2(vq.z, vq.w);
            unsigned long long s2[4] = {
                pk2(s01.x, s01.x), pk2(s01.y, s01.y),
                pk2(s23.x, s23.x), pk2(s23.y, s23.y)
            };
#pragma unroll
            for (int i = 0; i < 4; i++) {
                fma2(accY[i][0], s2[i], v01);
                fma2(accY[i][1], s2[i], v23);
            }
        }
    }

    // epilogue: * u, write [B,S,D] with head h at columns h*64..
#pragma unroll
    for (int i = 0; i < 4; i++) {
        int r = ty*4 + i;
        const float* urow = zb + (size_t)(s0 + r) * 2048 + uoff;
        float* yrow = Y + ((size_t)(b * S_LEN + s0 + r)) * DMODEL + h*64;
#pragma unroll
        for (int jp = 0; jp < 2; jp++) {
            float2 yv = up2(accY[i][jp]);
            int c = tx*4 + jp*2;
            yrow[c]     = yv.x * urow[c];
            yrow[c + 1] = yv.y * urow[c + 1];
        }
    }
}

// ---------------- 4) LayerNorm (optional fused residual) --------------------
__global__ void __launch_bounds__(128) ln_kernel(
    const float* __restrict__ x, const float* __restrict__ res,
    const float* __restrict__ w, const float* __restrict__ b,
    float* __restrict__ out)
{
    int row = blockIdx.x;
    int d = threadIdx.x * 4;
    size_t off = (size_t)row * DMODEL + d;
    float4 v = *(const float4*)(x + off);
    if (res) {
        float4 rv = *(const float4*)(res + off);
        v.x += rv.x; v.y += rv.y; v.z += rv.z; v.w += rv.w;
    }
    float s = v.x + v.y + v.z + v.w;
    float q = v.x*v.x + v.y*v.y + v.z*v.z + v.w*v.w;
#pragma unroll
    for (int o = 16; o > 0; o >>= 1) {
        s += __shfl_xor_sync(0xffffffffu, s, o);
        q += __shfl_xor_sync(0xffffffffu, q, o);
    }
    __shared__ float red[8];
    int warp = threadIdx.x >> 5;
    if ((threadIdx.x & 31) == 0) { red[warp] = s; red[4 + warp] = q; }
    __syncthreads();
    s = red[0] + red[1] + red[2] + red[3];
    q = red[4] + red[5] + red[6] + red[7];
    float mean = s * (1.f / 512.f);
    float var  = q * (1.f / 512.f) - mean * mean;
    float rs = rsqrtf(var + 1e-5f);
    float4 wv = *(const float4*)(w + d);
    float4 bv = *(const float4*)(b + d);
    float4 o4;
    o4.x = (v.x - mean) * rs * wv.x + bv.x;
    o4.y = (v.y - mean) * rs * wv.y + bv.y;
    o4.z = (v.z - mean) * rs * wv.z + bv.z;
    o4.w = (v.w - mean) * rs * wv.w + bv.w;
    *(float4*)(out + off) = o4;
}

// ---------------- launcher --------------------------------------------------
extern "C" void kernel_launch(void* const* d_in, const int* in_sizes, int n_in,
                              void* d_out, int out_size)
{
    (void)in_sizes; (void)n_in; (void)out_size;
    const int*   hii = (const int*)d_in[0];
    const int*   hci = (const int*)d_in[1];
    const int*   hl  = (const int*)d_in[2];
    const int*   ti  = (const int*)d_in[3];
    const int*   tc  = (const int*)d_in[4];
    const float* item_emb = (const float*)d_in[5];
    const float* cate_emb = (const float*)d_in[6];
    const float* seg_emb  = (const float*)d_in[7];
    const float* W1   = (const float*)d_in[8];
    const float* b1   = (const float*)d_in[9];
    const float* W2   = (const float*)d_in[10];
    const float* b2   = (const float*)d_in[11];
    const float* ln1w = (const float*)d_in[12];
    const float* ln1b = (const float*)d_in[13];
    const float* ln2w = (const float*)d_in[14];
    const float* ln2b = (const float*)d_in[15];
    const float* posw = (const float*)d_in[16];
    const float* lnfw = (const float*)d_in[17];
    const float* lnfb = (const float*)d_in[18];
    float* out = (float*)d_out;

    float *h_, *z_, *y_, *y2_;
    cudaGetSymbolAddress((void**)&h_,  g_h);
    cudaGetSymbolAddress((void**)&z_,  g_z);
    cudaGetSymbolAddress((void**)&y_,  g_y);
    cudaGetSymbolAddress((void**)&y2_, g_y2);

    const int ROWS = BATCH * S_LEN;  // 8192

    embed_kernel<<<ROWS, 128>>>(hii, hci, hl, ti, tc, item_emb, cate_emb, seg_emb);

    for (int l = 0; l < NLAYERS; l++) {
        gemm_kernel<1><<<dim3(2048/128, ROWS/128), 256>>>(
            h_, W1 + (size_t)l*512*2048, b1 + (size_t)l*2048, z_, ROWS, 2048, 512);
        attn_kernel<<<dim3(16, 64), 256>>>(z_, posw + (size_t)l*(2*MSLEN - 1), y_);
        ln_kernel<<<ROWS, 128>>>(y_, nullptr, ln1w + l*512, ln1b + l*512, y_);
        gemm_kernel<0><<<dim3(512/128, ROWS/128), 256>>>(
            y_, W2 + (size_t)l*512*512, b2 + (size_t)l*512, y2_, ROWS, 512, 512);
        ln_kernel<<<ROWS, 128>>>(y2_, h_, ln2w + l*512, ln2b + l*512, h_);
    }
    ln_kernel<<<ROWS, 128>>>(h_, nullptr, lnfw, lnfb, out);
}

// round 5
// speedup vs baseline: 1.1181x; 1.0871x over previous
#include <cuda_runtime.h>
#include <cuda_bf16.h>
#include <cstdint>
#include <math.h>

#define DMODEL 512
#define S_LEN 1024
#define BATCH 8
#define NHEADS 8
#define NLAYERS 4
#define MSLEN 2048

// ---------------- scratch (device globals; no allocations allowed) ----------
__device__ float g_h [BATCH * S_LEN * DMODEL];       // 16 MB
__device__ float g_z [BATCH * S_LEN * 4 * DMODEL];   // 64 MB
__device__ float g_y [BATCH * S_LEN * DMODEL];       // 16 MB
__device__ float g_y2[BATCH * S_LEN * DMODEL];       // 16 MB

// ---------------- packed f32x2 helpers (sm_10x FFMA2, used in attention) ----
__device__ __forceinline__ unsigned long long pk2(float lo, float hi) {
    unsigned long long r;
    asm("mov.b64 %0, {%1,%2};" : "=l"(r) : "f"(lo), "f"(hi));
    return r;
}
__device__ __forceinline__ float2 up2(unsigned long long v) {
    float2 r;
    asm("mov.b64 {%0,%1}, %2;" : "=f"(r.x), "=f"(r.y) : "l"(v));
    return r;
}
__device__ __forceinline__ void fma2(unsigned long long& d,
                                     unsigned long long a, unsigned long long b) {
    asm("fma.rn.f32x2 %0, %1, %2, %0;" : "+l"(d) : "l"(a), "l"(b));
}

__device__ __forceinline__ float silu_f(float x) {
    return __fdividef(x, 1.f + __expf(-x));
}

// ---------------- tf32 helpers ----------------------------------------------
__device__ __forceinline__ void tf32split(float x, uint32_t& hi, uint32_t& lo) {
    asm("cvt.rna.tf32.f32 %0, %1;" : "=r"(hi) : "f"(x));
    float r = x - __uint_as_float(hi);
    asm("cvt.rna.tf32.f32 %0, %1;" : "=r"(lo) : "f"(r));
}
__device__ __forceinline__ void mma_tf32(float* d, const uint32_t* a, const uint32_t* b) {
    asm volatile(
        "mma.sync.aligned.m16n8k8.row.col.f32.tf32.tf32.f32 "
        "{%0,%1,%2,%3}, {%4,%5,%6,%7}, {%8,%9}, {%0,%1,%2,%3};"
        : "+f"(d[0]), "+f"(d[1]), "+f"(d[2]), "+f"(d[3])
        : "r"(a[0]), "r"(a[1]), "r"(a[2]), "r"(a[3]), "r"(b[0]), "r"(b[1]));
}

// ---------------- 1) embedding gather + target splice -----------------------
__global__ void __launch_bounds__(128) embed_kernel(
    const int* __restrict__ hist_item, const int* __restrict__ hist_cate,
    const int* __restrict__ hist_len,  const int* __restrict__ tgt_item,
    const int* __restrict__ tgt_cate,  const float* __restrict__ item_emb,
    const float* __restrict__ cate_emb, const float* __restrict__ seg_emb)
{
    int bs = blockIdx.x;
    int b = bs >> 10, s = bs & 1023;
    int hl = hist_len[b];
    int id, cid, sg;
    if (s == hl)        { id = tgt_item[b];           cid = tgt_cate[b];           sg = 1; }
    else if (s < 1023)  { id = hist_item[b*1023 + s]; cid = hist_cate[b*1023 + s]; sg = 0; }
    else                { id = 0; cid = 0; sg = 0; }
    int d = threadIdx.x * 4;
    float4 a = *(const float4*)(item_emb + (size_t)id  * DMODEL + d);
    float4 c = *(const float4*)(cate_emb + (size_t)cid * DMODEL + d);
    float4 e = *(const float4*)(seg_emb  + (size_t)sg  * DMODEL + d);
    float4 o;
    o.x = a.x + c.x + e.x; o.y = a.y + c.y + e.y;
    o.z = a.z + c.z + e.z; o.w = a.w + c.w + e.w;
    *(float4*)(g_h + (size_t)bs * DMODEL + d) = o;
}

// ---------------- 2) 3xTF32 tensor-core GEMM --------------------------------
// C[M,N] = A[M,K] @ B[K,N] + bias, optional silu.
// BM=BN=128, BK=16, 256 threads = 8 warps (4 m x 2 n), warp tile 32x64.
// 3xTF32: a=hi+lo, b=hi+lo, D += ahi*bhi + ahi*blo + alo*bhi  (fp32-accurate).
template <int ACT>   // 0 = none, 1 = silu
__global__ void __launch_bounds__(256) gemm_kernel(
    const float* __restrict__ A, const float* __restrict__ B,
    const float* __restrict__ bias, float* __restrict__ C,
    int M, int N, int K)
{
    __shared__ uint32_t AsH[128][20];   // row-major [m][k], pitch 20: bank-clean frags
    __shared__ uint32_t AsL[128][20];
    __shared__ uint32_t BsH[16][136];   // [k][n], pitch 136: bank-clean frags
    __shared__ uint32_t BsL[16][136];

    const int tid  = threadIdx.x;
    const int lane = tid & 31, wid = tid >> 5;
    const int gid  = lane >> 2, tig = lane & 3;
    const int wm   = wid >> 1,  wn  = wid & 1;
    const int m0 = blockIdx.y * 128, n0 = blockIdx.x * 128;

    float acc[2][8][4];
#pragma unroll
    for (int mf = 0; mf < 2; mf++)
#pragma unroll
        for (int nf = 0; nf < 8; nf++)
#pragma unroll
            for (int e = 0; e < 4; e++) acc[mf][nf][e] = 0.f;

    const int ar = tid >> 2, ak = (tid & 3) * 4;   // A: 128 rows x 16 k
    const int bk = tid >> 5, bn = (tid & 31) * 4;  // B: 16 k x 128 n

    for (int k0 = 0; k0 < K; k0 += 16) {
        float4 a0 = *(const float4*)(A + (size_t)(m0 + ar)      * K + k0 + ak);
        float4 a1 = *(const float4*)(A + (size_t)(m0 + ar + 64) * K + k0 + ak);
        float4 b0 = *(const float4*)(B + (size_t)(k0 + bk)     * N + n0 + bn);
        float4 b1 = *(const float4*)(B + (size_t)(k0 + bk + 8) * N + n0 + bn);
        __syncthreads();   // previous tile's fragment reads complete
        {
            uint32_t h[4], l[4];
            tf32split(a0.x, h[0], l[0]); tf32split(a0.y, h[1], l[1]);
            tf32split(a0.z, h[2], l[2]); tf32split(a0.w, h[3], l[3]);
            *(uint4*)&AsH[ar][ak] = *(uint4*)h;
            *(uint4*)&AsL[ar][ak] = *(uint4*)l;
            tf32split(a1.x, h[0], l[0]); tf32split(a1.y, h[1], l[1]);
            tf32split(a1.z, h[2], l[2]); tf32split(a1.w, h[3], l[3]);
            *(uint4*)&AsH[ar + 64][ak] = *(uint4*)h;
            *(uint4*)&AsL[ar + 64][ak] = *(uint4*)l;
            tf32split(b0.x, h[0], l[0]); tf32split(b0.y, h[1], l[1]);
            tf32split(b0.z, h[2], l[2]); tf32split(b0.w, h[3], l[3]);
            *(uint4*)&BsH[bk][bn] = *(uint4*)h;
            *(uint4*)&BsL[bk][bn] = *(uint4*)l;
            tf32split(b1.x, h[0], l[0]); tf32split(b1.y, h[1], l[1]);
            tf32split(b1.z, h[2], l[2]); tf32split(b1.w, h[3], l[3]);
            *(uint4*)&BsH[bk + 8][bn] = *(uint4*)h;
            *(uint4*)&BsL[bk + 8][bn] = *(uint4*)l;
        }
        __syncthreads();

#pragma unroll
        for (int ks = 0; ks < 16; ks += 8) {
            uint32_t aH[2][4], aL[2][4];
#pragma unroll
            for (int mf = 0; mf < 2; mf++) {
                int row = wm * 32 + mf * 16 + gid;
                aH[mf][0] = AsH[row    ][ks + tig];
                aH[mf][1] = AsH[row + 8][ks + tig];
                aH[mf][2] = AsH[row    ][ks + tig + 4];
                aH[mf][3] = AsH[row + 8][ks + tig + 4];
                aL[mf][0] = AsL[row    ][ks + tig];
                aL[mf][1] = AsL[row + 8][ks + tig];
                aL[mf][2] = AsL[row    ][ks + tig + 4];
                aL[mf][3] = AsL[row + 8][ks + tig + 4];
            }
#pragma unroll
            for (int nf = 0; nf < 8; nf++) {
                int col = wn * 64 + nf * 8 + gid;
                uint32_t bH[2], bL[2];
                bH[0] = BsH[ks + tig    ][col];
                bH[1] = BsH[ks + tig + 4][col];
                bL[0] = BsL[ks + tig    ][col];
                bL[1] = BsL[ks + tig + 4][col];
#pragma unroll
                for (int mf = 0; mf < 2; mf++) {
                    mma_tf32(acc[mf][nf], aH[mf], bH);
                    mma_tf32(acc[mf][nf], aH[mf], bL);
                    mma_tf32(acc[mf][nf], aL[mf], bH);
                }
            }
        }
    }

    // epilogue: D frag layout c0:(gid, 2tig) c1:(gid, 2tig+1) c2:(gid+8,..) c3
#pragma unroll
    for (int mf = 0; mf < 2; mf++) {
        int r0 = m0 + wm * 32 + mf * 16 + gid;
#pragma unroll
        for (int nf = 0; nf < 8; nf++) {
            int c0 = n0 + wn * 64 + nf * 8 + tig * 2;
            float bx = bias[c0], by = bias[c0 + 1];
            float v0 = acc[mf][nf][0] + bx, v1 = acc[mf][nf][1] + by;
            float v2 = acc[mf][nf][2] + bx, v3 = acc[mf][nf][3] + by;
            if (ACT) { v0 = silu_f(v0); v1 = silu_f(v1); v2 = silu_f(v2); v3 = silu_f(v3); }
            float2 lo2; lo2.x = v0; lo2.y = v1;
            float2 hi2; hi2.x = v2; hi2.y = v3;
            *(float2*)(C + (size_t)r0 * N + c0)       = lo2;
            *(float2*)(C + (size_t)(r0 + 8) * N + c0) = hi2;
        }
    }
}

// ---------------- 3) HSTU attention: y = (silu(QK^T + bias) * causal) @ V * U
__global__ void __launch_bounds__(256) attn_kernel(
    const float* __restrict__ Z, const float* __restrict__ pw,
    float* __restrict__ Y)
{
    __shared__ float Qs[64 * 66];
    __shared__ float Ks[32 * 66];   // padded K; later aliased as St[t][r]
    __shared__ float Vs[32 * 64];
    __shared__ float bias_s[96];

    const int sb = blockIdx.x, bh = blockIdx.y;
    const int b = bh >> 3, h = bh & 7;
    const float* zb = Z + (size_t)b * S_LEN * 2048;
    const int s0 = sb * 64;
    const int tid = threadIdx.x;
    const int tx = tid & 15, ty = tid >> 4;   // AV-phase map (4 rows x 4 dims)
    const int cx = tid & 7,  ry = tid >> 3;   // score-phase map (2 rows x 4 t)
    const int uoff = h * 64, qoff = 512 + h * 64, koff = 1024 + h * 64, voff = 1536 + h * 64;

#pragma unroll
    for (int it = 0; it < 4; it++) {
        int f = tid + it * 256;
        int r = f >> 4, c = (f & 15) * 4;
        float4 q4 = *(const float4*)(zb + (size_t)(s0 + r) * 2048 + qoff + c);
        Qs[r*66 + c+0] = q4.x; Qs[r*66 + c+1] = q4.y;
        Qs[r*66 + c+2] = q4.z; Qs[r*66 + c+3] = q4.w;
    }

    unsigned long long accY[4][2];
#pragma unroll
    for (int i = 0; i < 4; i++) { accY[i][0] = 0ull; accY[i][1] = 0ull; }

    const int nkt = 2 * sb + 2;
    for (int kt = 0; kt < nkt; kt++) {
        const int t0 = kt * 32;
        __syncthreads();
#pragma unroll
        for (int it = 0; it < 2; it++) {
            int f = tid + it * 256;
            int r = f >> 4, c = (f & 15) * 4;
            float4 k4 = *(const float4*)(zb + (size_t)(t0 + r) * 2048 + koff + c);
            Ks[r*66 + c+0] = k4.x; Ks[r*66 + c+1] = k4.y;
            Ks[r*66 + c+2] = k4.z; Ks[r*66 + c+3] = k4.w;
            float4 v4 = *(const float4*)(zb + (size_t)(t0 + r) * 2048 + voff + c);
            *(float4*)&Vs[r*64 + c] = v4;
        }
        const int base = MSLEN - 1 + t0 - s0;
        if (tid < 95) bias_s[tid] = pw[base - 63 + tid];
        __syncthreads();

        unsigned long long sa[2][4];
#pragma unroll
        for (int i = 0; i < 2; i++)
#pragma unroll
            for (int j = 0; j < 4; j++) sa[i][j] = 0ull;
#pragma unroll
        for (int d = 0; d < 64; d += 2) {
            unsigned long long q0 = *(const unsigned long long*)&Qs[(ry*2+0)*66 + d];
            unsigned long long q1 = *(const unsigned long long*)&Qs[(ry*2+1)*66 + d];
            unsigned long long kv[4];
#pragma unroll
            for (int j = 0; j < 4; j++)
                kv[j] = *(const unsigned long long*)&Ks[(cx*4 + j)*66 + d];
#pragma unroll
            for (int j = 0; j < 4; j++) {
                fma2(sa[0][j], q0, kv[j]);
                fma2(sa[1][j], q1, kv[j]);
            }
        }
        __syncthreads();

#pragma unroll
        for (int i = 0; i < 2; i++) {
            int r = ry*2 + i;
#pragma unroll
            for (int j = 0; j < 4; j++) {
                int c = cx*4 + j;
                float2 p = up2(sa[i][j]);
                float x = p.x + p.y + bias_s[63 + c - r];
                float sl = silu_f(x);
                if (t0 + c > s0 + r) sl = 0.f;
                Ks[c*66 + r] = sl;
            }
        }
        __syncthreads();

#pragma unroll
        for (int t = 0; t < 32; t++) {
            float2 s01 = *(const float2*)&Ks[t*66 + ty*4];
            float2 s23 = *(const float2*)&Ks[t*66 + ty*4 + 2];
            float4 vq  = *(const float4*)&Vs[t*64 + tx*4];
            unsigned long long v01 = pk2(vq.x, vq.y);
            unsigned long long v23 = pk2(vq.z, vq.w);
            unsigned long long s2[4] = {
                pk2(s01.x, s01.x), pk2(s01.y, s01.y),
                pk2(s23.x, s23.x), pk2(s23.y, s23.y)
            };
#pragma unroll
            for (int i = 0; i < 4; i++) {
                fma2(accY[i][0], s2[i], v01);
                fma2(accY[i][1], s2[i], v23);
            }
        }
    }

#pragma unroll
    for (int i = 0; i < 4; i++) {
        int r = ty*4 + i;
        const float* urow = zb + (size_t)(s0 + r) * 2048 + uoff;
        float* yrow = Y + ((size_t)(b * S_LEN + s0 + r)) * DMODEL + h*64;
#pragma unroll
        for (int jp = 0; jp < 2; jp++) {
            float2 yv = up2(accY[i][jp]);
            int c = tx*4 + jp*2;
            yrow[c]     = yv.x * urow[c];
            yrow[c + 1] = yv.y * urow[c + 1];
        }
    }
}

// ---------------- 4) LayerNorm (optional fused residual) --------------------
__global__ void __launch_bounds__(128) ln_kernel(
    const float* __restrict__ x, const float* __restrict__ res,
    const float* __restrict__ w, const float* __restrict__ b,
    float* __restrict__ out)
{
    int row = blockIdx.x;
    int d = threadIdx.x * 4;
    size_t off = (size_t)row * DMODEL + d;
    float4 v = *(const float4*)(x + off);
    if (res) {
        float4 rv = *(const float4*)(res + off);
        v.x += rv.x; v.y += rv.y; v.z += rv.z; v.w += rv.w;
    }
    float s = v.x + v.y + v.z + v.w;
    float q = v.x*v.x + v.y*v.y + v.z*v.z + v.w*v.w;
#pragma unroll
    for (int o = 16; o > 0; o >>= 1) {
        s += __shfl_xor_sync(0xffffffffu, s, o);
        q += __shfl_xor_sync(0xffffffffu, q, o);
    }
    __shared__ float red[8];
    int warp = threadIdx.x >> 5;
    if ((threadIdx.x & 31) == 0) { red[warp] = s; red[4 + warp] = q; }
    __syncthreads();
    s = red[0] + red[1] + red[2] + red[3];
    q = red[4] + red[5] + red[6] + red[7];
    float mean = s * (1.f / 512.f);
    float var  = q * (1.f / 512.f) - mean * mean;
    float rs = rsqrtf(var + 1e-5f);
    float4 wv = *(const float4*)(w + d);
    float4 bv = *(const float4*)(b + d);
    float4 o4;
    o4.x = (v.x - mean) * rs * wv.x + bv.x;
    o4.y = (v.y - mean) * rs * wv.y + bv.y;
    o4.z = (v.z - mean) * rs * wv.z + bv.z;
    o4.w = (v.w - mean) * rs * wv.w + bv.w;
    *(float4*)(out + off) = o4;
}

// ---------------- launcher --------------------------------------------------
extern "C" void kernel_launch(void* const* d_in, const int* in_sizes, int n_in,
                              void* d_out, int out_size)
{
    (void)in_sizes; (void)n_in; (void)out_size;
    const int*   hii = (const int*)d_in[0];
    const int*   hci = (const int*)d_in[1];
    const int*   hl  = (const int*)d_in[2];
    const int*   ti  = (const int*)d_in[3];
    const int*   tc  = (const int*)d_in[4];
    const float* item_emb = (const float*)d_in[5];
    const float* cate_emb = (const float*)d_in[6];
    const float* seg_emb  = (const float*)d_in[7];
    const float* W1   = (const float*)d_in[8];
    const float* b1   = (const float*)d_in[9];
    const float* W2   = (const float*)d_in[10];
    const float* b2   = (const float*)d_in[11];
    const float* ln1w = (const float*)d_in[12];
    const float* ln1b = (const float*)d_in[13];
    const float* ln2w = (const float*)d_in[14];
    const float* ln2b = (const float*)d_in[15];
    const float* posw = (const float*)d_in[16];
    const float* lnfw = (const float*)d_in[17];
    const float* lnfb = (const float*)d_in[18];
    float* out = (float*)d_out;

    float *h_, *z_, *y_, *y2_;
    cudaGetSymbolAddress((void**)&h_,  g_h);
    cudaGetSymbolAddress((void**)&z_,  g_z);
    cudaGetSymbolAddress((void**)&y_,  g_y);
    cudaGetSymbolAddress((void**)&y2_, g_y2);

    const int ROWS = BATCH * S_LEN;  // 8192

    embed_kernel<<<ROWS, 128>>>(hii, hci, hl, ti, tc, item_emb, cate_emb, seg_emb);

    for (int l = 0; l < NLAYERS; l++) {
        gemm_kernel<1><<<dim3(2048/128, ROWS/128), 256>>>(
            h_, W1 + (size_t)l*512*2048, b1 + (size_t)l*2048, z_, ROWS, 2048, 512);
        attn_kernel<<<dim3(16, 64), 256>>>(z_, posw + (size_t)l*(2*MSLEN - 1), y_);
        ln_kernel<<<ROWS, 128>>>(y_, nullptr, ln1w + l*512, ln1b + l*512, y_);
        gemm_kernel<0><<<dim3(512/128, ROWS/128), 256>>>(
            y_, W2 + (size_t)l*512*512, b2 + (size_t)l*512, y2_, ROWS, 512, 512);
        ln_kernel<<<ROWS, 128>>>(y2_, h_, ln2w + l*512, ln2b + l*512, h_);
    }
    ln_kernel<<<ROWS, 128>>>(h_, nullptr, lnfw, lnfb, out);
}

// round 7
// speedup vs baseline: 1.2994x; 1.1622x over previous
#include <cuda_runtime.h>
#include <cuda_bf16.h>
#include <cstdint>
#include <math.h>

#define DMODEL 512
#define S_LEN 1024
#define BATCH 8
#define NLAYERS 4
#define MSLEN 2048
#define ROWS_TOT (BATCH * S_LEN)

// ---------------- scratch (device globals; no allocations allowed) ----------
__device__ float g_h [ROWS_TOT * DMODEL];
__device__ float g_z [ROWS_TOT * 4 * DMODEL];
__device__ float g_y [ROWS_TOT * DMODEL];
__device__ float g_y2[ROWS_TOT * DMODEL];
__device__ __nv_bfloat16 g_hh[ROWS_TOT * DMODEL], g_hl[ROWS_TOT * DMODEL];
__device__ __nv_bfloat16 g_yh[ROWS_TOT * DMODEL], g_yl[ROWS_TOT * DMODEL];
__device__ __nv_bfloat16 g_w1h[NLAYERS * 2048 * 512], g_w1l[NLAYERS * 2048 * 512];
__device__ __nv_bfloat16 g_w2h[NLAYERS * 512 * 512],  g_w2l[NLAYERS * 512 * 512];

// ---------------- small helpers ---------------------------------------------
__device__ __forceinline__ float silu_f(float x) {
    return __fdividef(x, 1.f + __expf(-x));
}
__device__ __forceinline__ void bf16split(float x, __nv_bfloat16& h, __nv_bfloat16& l) {
    h = __float2bfloat16(x);
    l = __float2bfloat16(x - __bfloat162float(h));
}

// packed f32x2 (attention)
__device__ __forceinline__ unsigned long long pk2(float lo, float hi) {
    unsigned long long r;
    asm("mov.b64 %0, {%1,%2};" : "=l"(r) : "f"(lo), "f"(hi));
    return r;
}
__device__ __forceinline__ float2 up2(unsigned long long v) {
    float2 r;
    asm("mov.b64 {%0,%1}, %2;" : "=f"(r.x), "=f"(r.y) : "l"(v));
    return r;
}
__device__ __forceinline__ void fma2(unsigned long long& d,
                                     unsigned long long a, unsigned long long b) {
    asm("fma.rn.f32x2 %0, %1, %2, %0;" : "+l"(d) : "l"(a), "l"(b));
}

// ---------------- mma.sync bf16 + cp.async primitives ------------------------
__device__ __forceinline__ uint32_t smem_u32(const void* p) {
    uint32_t a;
    asm("{ .reg .u64 t; cvta.to.shared.u64 t, %1; cvt.u32.u64 %0, t; }" : "=r"(a) : "l"(p));
    return a;
}
__device__ __forceinline__ void mma_bf16(float* d, const uint32_t* a, const uint32_t* b) {
    asm volatile(
        "mma.sync.aligned.m16n8k16.row.col.f32.bf16.bf16.f32 "
        "{%0,%1,%2,%3}, {%4,%5,%6,%7}, {%8,%9}, {%0,%1,%2,%3};"
        : "+f"(d[0]), "+f"(d[1]), "+f"(d[2]), "+f"(d[3])
        : "r"(a[0]), "r"(a[1]), "r"(a[2]), "r"(a[3]), "r"(b[0]), "r"(b[1]));
}
__device__ __forceinline__ void cp16(uint32_t dst, const void* src) {
    asm volatile("cp.async.cg.shared.global [%0], [%1], 16;" :: "r"(dst), "l"(src));
}
#define CP_COMMIT() asm volatile("cp.async.commit_group;" ::: "memory")
#define CP_WAIT(n)  asm volatile("cp.async.wait_group %0;" :: "n"(n) : "memory")

// ---------------- weight transpose + bf16 split: W[L][K][N] -> WT[L][N][K] --
__global__ void __launch_bounds__(256) wsplit_kernel(
    const float* __restrict__ W, __nv_bfloat16* __restrict__ Th,
    __nv_bfloat16* __restrict__ Tl, int K, int N)
{
    __shared__ float t[32][33];
    int l = blockIdx.z;
    int k0 = blockIdx.x * 32, n0 = blockIdx.y * 32;
    const float* w = W + (size_t)l * K * N;
    int tx = threadIdx.x, ty = threadIdx.y;   // 32 x 8
#pragma unroll
    for (int i = 0; i < 4; i++)
        t[ty + i*8][tx] = w[(size_t)(k0 + ty + i*8) * N + n0 + tx];
    __syncthreads();
#pragma unroll
    for (int i = 0; i < 4; i++) {
        float v = t[tx][ty + i*8];
        __nv_bfloat16 h, lo;
        bf16split(v, h, lo);
        size_t o = (size_t)l * N * K + (size_t)(n0 + ty + i*8) * K + k0 + tx;
        Th[o] = h; Tl[o] = lo;
    }
}

// ---------------- 1) embedding gather + target splice + bf16 split ----------
__global__ void __launch_bounds__(128) embed_kernel(
    const int* __restrict__ hist_item, const int* __restrict__ hist_cate,
    const int* __restrict__ hist_len,  const int* __restrict__ tgt_item,
    const int* __restrict__ tgt_cate,  const float* __restrict__ item_emb,
    const float* __restrict__ cate_emb, const float* __restrict__ seg_emb,
    int row0)
{
    int bs = blockIdx.x + row0;
    int b = bs >> 10, s = bs & 1023;
    int hl = hist_len[b];
    int id, cid, sg;
    if (s == hl)        { id = tgt_item[b];           cid = tgt_cate[b];           sg = 1; }
    else if (s < 1023)  { id = hist_item[b*1023 + s]; cid = hist_cate[b*1023 + s]; sg = 0; }
    else                { id = 0; cid = 0; sg = 0; }
    int d = threadIdx.x * 4;
    float4 a = *(const float4*)(item_emb + (size_t)id  * DMODEL + d);
    float4 c = *(const float4*)(cate_emb + (size_t)cid * DMODEL + d);
    float4 e = *(const float4*)(seg_emb  + (size_t)sg  * DMODEL + d);
    float o[4];
    o[0] = a.x + c.x + e.x; o[1] = a.y + c.y + e.y;
    o[2] = a.z + c.z + e.z; o[3] = a.w + c.w + e.w;
    size_t off = (size_t)bs * DMODEL + d;
    *(float4*)(g_h + off) = *(float4*)o;
    __nv_bfloat16 hh[4], ll[4];
#pragma unroll
    for (int i = 0; i < 4; i++) bf16split(o[i], hh[i], ll[i]);
    *(uint64_t*)(g_hh + off) = *(uint64_t*)hh;
    *(uint64_t*)(g_hl + off) = *(uint64_t*)ll;
}

// ---------------- 2) bf16 3-term tensor GEMM (mma.sync m16n8k16) ------------
// C[M,N] = A[M,K] @ BT[N,K]^T + bias; A/B pre-split hi/lo bf16, K-major rows.
// CTA 128x128, BK=32 bf16, double-buffered cp.async, 8 warps (4m x 2n).
// Emulated fp32: D += Ah*Bh + Ah*Bl + Al*Bh.
#define GP 20                     // smem pitch in uint32 (16 used) - bank-clean
#define TILE_U (128 * GP)         // uint32 per tile (2560)
#define BUF_U  (4 * TILE_U)       // uint32 per buffer (4 tiles)
#define GEMM_SMEM (2 * BUF_U * 4) // bytes (81920)

template <int ACT>
__global__ void __launch_bounds__(256) gemm_bf(
    const __nv_bfloat16* __restrict__ Ah, const __nv_bfloat16* __restrict__ Al,
    const __nv_bfloat16* __restrict__ Bh, const __nv_bfloat16* __restrict__ Bl,
    const float* __restrict__ bias, float* __restrict__ C, int N, int K)
{
    extern __shared__ uint32_t sm[];
    const uint32_t sbase = smem_u32(sm);
    const int tid = threadIdx.x, lane = tid & 31, wid = tid >> 5;
    const int gid = lane >> 2, tig = lane & 3;
    const int wm = wid >> 1, wn = wid & 1;
    const int m0 = blockIdx.y * 128, n0 = blockIdx.x * 128;

    const __nv_bfloat16* srcs[4] = { Ah + (size_t)m0 * K, Al + (size_t)m0 * K,
                                     Bh + (size_t)n0 * K, Bl + (size_t)n0 * K };

    float acc[2][8][4];
#pragma unroll
    for (int mf = 0; mf < 2; mf++)
#pragma unroll
        for (int nf = 0; nf < 8; nf++)
#pragma unroll
            for (int e = 0; e < 4; e++) acc[mf][nf][e] = 0.f;

    const int r0 = tid >> 2;            // 0..63
    const int cB = (tid & 3) * 16;      // byte offset within 64B k-chunk row
    const size_t rowB = (size_t)K * 2;  // row stride bytes

    const int nchunks = K >> 5;         // BK=32

    // preload chunk 0
    {
        const size_t koff = 0;
#pragma unroll
        for (int t = 0; t < 4; t++) {
            const char* s = (const char*)srcs[t] + koff;
            uint32_t d0 = sbase + t * (TILE_U * 4);
            cp16(d0 + r0 * (GP * 4) + cB,        s + (size_t)r0 * rowB + cB);
            cp16(d0 + (r0 + 64) * (GP * 4) + cB, s + (size_t)(r0 + 64) * rowB + cB);
        }
        CP_COMMIT();
    }

    for (int c = 0; c < nchunks; c++) {
        if (c + 1 < nchunks) {
            const size_t koff = (size_t)(c + 1) * 64;   // 32 bf16 = 64 B
            const uint32_t bb = ((c + 1) & 1) * (BUF_U * 4);
#pragma unroll
            for (int t = 0; t < 4; t++) {
                const char* s = (const char*)srcs[t] + koff;
                uint32_t d0 = sbase + bb + t * (TILE_U * 4);
                cp16(d0 + r0 * (GP * 4) + cB,        s + (size_t)r0 * rowB + cB);
                cp16(d0 + (r0 + 64) * (GP * 4) + cB, s + (size_t)(r0 + 64) * rowB + cB);
            }
            CP_COMMIT();
            CP_WAIT(1);
        } else {
            CP_WAIT(0);
        }
        __syncthreads();

        const uint32_t* AhT = sm + (c & 1) * BUF_U;
        const uint32_t* AlT = AhT + TILE_U;
        const uint32_t* BhT = AhT + 2 * TILE_U;
        const uint32_t* BlT = AhT + 3 * TILE_U;

#pragma unroll
        for (int ks = 0; ks < 2; ks++) {
            uint32_t ah[2][4], al[2][4];
#pragma unroll
            for (int mf = 0; mf < 2; mf++) {
                int row = wm * 32 + mf * 16 + gid;
                int ca = ks * 8 + tig;
                ah[mf][0] = AhT[row * GP + ca];
                ah[mf][1] = AhT[(row + 8) * GP + ca];
                ah[mf][2] = AhT[row * GP + ca + 4];
                ah[mf][3] = AhT[(row + 8) * GP + ca + 4];
                al[mf][0] = AlT[row * GP + ca];
                al[mf][1] = AlT[(row + 8) * GP + ca];
                al[mf][2] = AlT[row * GP + ca + 4];
                al[mf][3] = AlT[(row + 8) * GP + ca + 4];
            }
#pragma unroll
            for (int nf = 0; nf < 8; nf++) {
                int n = wn * 64 + nf * 8 + gid;
                int cb = ks * 8 + tig;
                uint32_t bh[2] = { BhT[n * GP + cb], BhT[n * GP + cb + 4] };
                uint32_t bl[2] = { BlT[n * GP + cb], BlT[n * GP + cb + 4] };
#pragma unroll
                for (int mf = 0; mf < 2; mf++) {
                    mma_bf16(acc[mf][nf], ah[mf], bh);
                    mma_bf16(acc[mf][nf], ah[mf], bl);
                    mma_bf16(acc[mf][nf], al[mf], bh);
                }
            }
        }
        __syncthreads();
    }

    // epilogue: d0:(gid, 2tig) d1:(gid, 2tig+1) d2:(gid+8, 2tig) d3:(gid+8, 2tig+1)
#pragma unroll
    for (int mf = 0; mf < 2; mf++) {
        int r = m0 + wm * 32 + mf * 16 + gid;
#pragma unroll
        for (int nf = 0; nf < 8; nf++) {
            int c0 = n0 + wn * 64 + nf * 8 + tig * 2;
            float bx = bias[c0], by = bias[c0 + 1];
            float v0 = acc[mf][nf][0] + bx, v1 = acc[mf][nf][1] + by;
            float v2 = acc[mf][nf][2] + bx, v3 = acc[mf][nf][3] + by;
            if (ACT) { v0 = silu_f(v0); v1 = silu_f(v1); v2 = silu_f(v2); v3 = silu_f(v3); }
            float2 lo2; lo2.x = v0; lo2.y = v1;
            float2 hi2; hi2.x = v2; hi2.y = v3;
            *(float2*)(C + (size_t)r * N + c0)       = lo2;
            *(float2*)(C + (size_t)(r + 8) * N + c0) = hi2;
        }
    }
}

// ---------------- 3) HSTU attention (f32x2 SIMT) -----------------------------
__global__ void __launch_bounds__(256) attn_kernel(
    const float* __restrict__ Z, const float* __restrict__ pw,
    float* __restrict__ Y)
{
    __shared__ float Qs[64 * 66];
    __shared__ float Ks[32 * 66];
    __shared__ float Vs[32 * 64];
    __shared__ float bias_s[96];

    const int sb = blockIdx.x, bh = blockIdx.y;
    const int b = bh >> 3, h = bh & 7;
    const float* zb = Z + (size_t)b * S_LEN * 2048;
    const int s0 = sb * 64;
    const int tid = threadIdx.x;
    const int tx = tid & 15, ty = tid >> 4;
    const int cx = tid & 7,  ry = tid >> 3;
    const int uoff = h * 64, qoff = 512 + h * 64, koff = 1024 + h * 64, voff = 1536 + h * 64;

#pragma unroll
    for (int it = 0; it < 4; it++) {
        int f = tid + it * 256;
        int r = f >> 4, c = (f & 15) * 4;
        float4 q4 = *(const float4*)(zb + (size_t)(s0 + r) * 2048 + qoff + c);
        Qs[r*66 + c+0] = q4.x; Qs[r*66 + c+1] = q4.y;
        Qs[r*66 + c+2] = q4.z; Qs[r*66 + c+3] = q4.w;
    }

    unsigned long long accY[4][2];
#pragma unroll
    for (int i = 0; i < 4; i++) { accY[i][0] = 0ull; accY[i][1] = 0ull; }

    const int nkt = 2 * sb + 2;
    for (int kt = 0; kt < nkt; kt++) {
        const int t0 = kt * 32;
        __syncthreads();
#pragma unroll
        for (int it = 0; it < 2; it++) {
            int f = tid + it * 256;
            int r = f >> 4, c = (f & 15) * 4;
            float4 k4 = *(const float4*)(zb + (size_t)(t0 + r) * 2048 + koff + c);
            Ks[r*66 + c+0] = k4.x; Ks[r*66 + c+1] = k4.y;
            Ks[r*66 + c+2] = k4.z; Ks[r*66 + c+3] = k4.w;
            float4 v4 = *(const float4*)(zb + (size_t)(t0 + r) * 2048 + voff + c);
            *(float4*)&Vs[r*64 + c] = v4;
        }
        const int base = MSLEN - 1 + t0 - s0;
        if (tid < 95) bias_s[tid] = pw[base - 63 + tid];
        __syncthreads();

        unsigned long long sa[2][4];
#pragma unroll
        for (int i = 0; i < 2; i++)
#pragma unroll
            for (int j = 0; j < 4; j++) sa[i][j] = 0ull;
#pragma unroll
        for (int d = 0; d < 64; d += 2) {
            unsigned long long q0 = *(const unsigned long long*)&Qs[(ry*2+0)*66 + d];
            unsigned long long q1 = *(const unsigned long long*)&Qs[(ry*2+1)*66 + d];
            unsigned long long kv[4];
#pragma unroll
            for (int j = 0; j < 4; j++)
                kv[j] = *(const unsigned long long*)&Ks[(cx*4 + j)*66 + d];
#pragma unroll
            for (int j = 0; j < 4; j++) {
                fma2(sa[0][j], q0, kv[j]);
                fma2(sa[1][j], q1, kv[j]);
            }
        }
        __syncthreads();

#pragma unroll
        for (int i = 0; i < 2; i++) {
            int r = ry*2 + i;
#pragma unroll
            for (int j = 0; j < 4; j++) {
                int c = cx*4 + j;
                float2 p = up2(sa[i][j]);
                float x = p.x + p.y + bias_s[63 + c - r];
                float sl = silu_f(x);
                if (t0 + c > s0 + r) sl = 0.f;
                Ks[c*66 + r] = sl;
            }
        }
        __syncthreads();

#pragma unroll
        for (int t = 0; t < 32; t++) {
            float2 s01 = *(const float2*)&Ks[t*66 + ty*4];
            float2 s23 = *(const float2*)&Ks[t*66 + ty*4 + 2];
            float4 vq  = *(const float4*)&Vs[t*64 + tx*4];
            unsigned long long v01 = pk2(vq.x, vq.y);
            unsigned long long v23 = pk2(vq.z, vq.w);
            unsigned long long s2[4] = {
                pk2(s01.x, s01.x), pk2(s01.y, s01.y),
                pk2(s23.x, s23.x), pk2(s23.y, s23.y)
            };
#pragma unroll
            for (int i = 0; i < 4; i++) {
                fma2(accY[i][0], s2[i], v01);
                fma2(accY[i][1], s2[i], v23);
            }
        }
    }

#pragma unroll
    for (int i = 0; i < 4; i++) {
        int r = ty*4 + i;
        const float* urow = zb + (size_t)(s0 + r) * 2048 + uoff;
        float* yrow = Y + ((size_t)(b * S_LEN + s0 + r)) * DMODEL + h*64;
#pragma unroll
        for (int jp = 0; jp < 2; jp++) {
            float2 yv = up2(accY[i][jp]);
            int c = tx*4 + jp*2;
            yrow[c]     = yv.x * urow[c];
            yrow[c + 1] = yv.y * urow[c + 1];
        }
    }
}

// ---------------- 4) LayerNorm: fp32 and/or bf16-split outputs --------------
template <int WF32, int WBF>
__global__ void __launch_bounds__(128) ln_kernel(
    const float* __restrict__ x, const float* __restrict__ res,
    const float* __restrict__ w, const float* __restrict__ b,
    float* __restrict__ out, __nv_bfloat16* __restrict__ oh,
    __nv_bfloat16* __restrict__ ol)
{
    int row = blockIdx.x;
    int d = threadIdx.x * 4;
    size_t off = (size_t)row * DMODEL + d;
    float4 v = *(const float4*)(x + off);
    if (res) {
        float4 rv = *(const float4*)(res + off);
        v.x += rv.x; v.y += rv.y; v.z += rv.z; v.w += rv.w;
    }
    float s = v.x + v.y + v.z + v.w;
    float q = v.x*v.x + v.y*v.y + v.z*v.z + v.w*v.w;
#pragma unroll
    for (int o = 16; o > 0; o >>= 1) {
        s += __shfl_xor_sync(0xffffffffu, s, o);
        q += __shfl_xor_sync(0xffffffffu, q, o);
    }
    __shared__ float red[8];
    int warp = threadIdx.x >> 5;
    if ((threadIdx.x & 31) == 0) { red[warp] = s; red[4 + warp] = q; }
    __syncthreads();
    s = red[0] + red[1] + red[2] + red[3];
    q = red[4] + red[5] + red[6] + red[7];
    float mean = s * (1.f / 512.f);
    float var  = q * (1.f / 512.f) - mean * mean;
    float rs = rsqrtf(var + 1e-5f);
    float4 wv = *(const float4*)(w + d);
    float4 bv = *(const float4*)(b + d);
    float o4[4];
    o4[0] = (v.x - mean) * rs * wv.x + bv.x;
    o4[1] = (v.y - mean) * rs * wv.y + bv.y;
    o4[2] = (v.z - mean) * rs * wv.z + bv.z;
    o4[3] = (v.w - mean) * rs * wv.w + bv.w;
    if (WF32) *(float4*)(out + off) = *(float4*)o4;
    if (WBF) {
        __nv_bfloat16 hh[4], ll[4];
#pragma unroll
        for (int i = 0; i < 4; i++) bf16split(o4[i], hh[i], ll[i]);
        *(uint64_t*)(oh + off) = *(uint64_t*)hh;
        *(uint64_t*)(ol + off) = *(uint64_t*)ll;
    }
}

// ---------------- launcher --------------------------------------------------
extern "C" void kernel_launch(void* const* d_in, const int* in_sizes, int n_in,
                              void* d_out, int out_size)
{
    (void)in_sizes; (void)n_in; (void)out_size;
    const int*   hii = (const int*)d_in[0];
    const int*   hci = (const int*)d_in[1];
    const int*   hl  = (const int*)d_in[2];
    const int*   ti  = (const int*)d_in[3];
    const int*   tc  = (const int*)d_in[4];
    const float* item_emb = (const float*)d_in[5];
    const float* cate_emb = (const float*)d_in[6];
    const float* seg_emb  = (const float*)d_in[7];
    const float* W1   = (const float*)d_in[8];
    const float* b1   = (const float*)d_in[9];
    const float* W2   = (const float*)d_in[10];
    const float* b2   = (const float*)d_in[11];
    const float* ln1w = (const float*)d_in[12];
    const float* ln1b = (const float*)d_in[13];
    const float* ln2w = (const float*)d_in[14];
    const float* ln2b = (const float*)d_in[15];
    const float* posw = (const float*)d_in[16];
    const float* lnfw = (const float*)d_in[17];
    const float* lnfb = (const float*)d_in[18];
    float* out = (float*)d_out;

    float *h_, *z_, *y_, *y2_;
    __nv_bfloat16 *hh_, *hlm_, *yh_, *yl_, *w1h_, *w1l_, *w2h_, *w2l_;
    cudaGetSymbolAddress((void**)&h_,   g_h);
    cudaGetSymbolAddress((void**)&z_,   g_z);
    cudaGetSymbolAddress((void**)&y_,   g_y);
    cudaGetSymbolAddress((void**)&y2_,  g_y2);
    cudaGetSymbolAddress((void**)&hh_,  g_hh);
    cudaGetSymbolAddress((void**)&hlm_, g_hl);
    cudaGetSymbolAddress((void**)&yh_,  g_yh);
    cudaGetSymbolAddress((void**)&yl_,  g_yl);
    cudaGetSymbolAddress((void**)&w1h_, g_w1h);
    cudaGetSymbolAddress((void**)&w1l_, g_w1l);
    cudaGetSymbolAddress((void**)&w2h_, g_w2h);
    cudaGetSymbolAddress((void**)&w2l_, g_w2l);

    cudaFuncSetAttribute(gemm_bf<0>, cudaFuncAttributeMaxDynamicSharedMemorySize, GEMM_SMEM);
    cudaFuncSetAttribute(gemm_bf<1>, cudaFuncAttributeMaxDynamicSharedMemorySize, GEMM_SMEM);

    const int ROWS = ROWS_TOT;  // 8192

    // launches 1-2: weight transpose+split; 3-5: embed chunks (-> gemm1 = #6 for ncu -s 5)
    wsplit_kernel<<<dim3(16, 64, NLAYERS), dim3(32, 8)>>>(W1, w1h_, w1l_, 512, 2048);
    wsplit_kernel<<<dim3(16, 16, NLAYERS), dim3(32, 8)>>>(W2, w2h_, w2l_, 512, 512);
    embed_kernel<<<4096, 128>>>(hii, hci, hl, ti, tc, item_emb, cate_emb, seg_emb, 0);
    embed_kernel<<<2048, 128>>>(hii, hci, hl, ti, tc, item_emb, cate_emb, seg_emb, 4096);
    embed_kernel<<<2048, 128>>>(hii, hci, hl, ti, tc, item_emb, cate_emb, seg_emb, 6144);

    for (int l = 0; l < NLAYERS; l++) {
        gemm_bf<1><<<dim3(2048/128, ROWS/128), 256, GEMM_SMEM>>>(
            hh_, hlm_, w1h_ + (size_t)l*2048*512, w1l_ + (size_t)l*2048*512,
            b1 + (size_t)l*2048, z_, 2048, 512);
        attn_kernel<<<dim3(16, 64), 256>>>(z_, posw + (size_t)l*(2*MSLEN - 1), y_);
        ln_kernel<0,1><<<ROWS, 128>>>(y_, nullptr, ln1w + l*512, ln1b + l*512,
                                      nullptr, yh_, yl_);
        gemm_bf<0><<<dim3(512/128, ROWS/128), 256, GEMM_SMEM>>>(
            yh_, yl_, w2h_ + (size_t)l*512*512, w2l_ + (size_t)l*512*512,
            b2 + (size_t)l*512, y2_, 512, 512);
        ln_kernel<1,1><<<ROWS, 128>>>(y2_, h_, ln2w + l*512, ln2b + l*512,
                                      h_, hh_, hlm_);
    }
    ln_kernel<1,0><<<ROWS, 128>>>(h_, nullptr, lnfw, lnfb, out, nullptr, nullptr);
}